// round 1
// baseline (speedup 1.0000x reference)
#include <cuda_runtime.h>

namespace {
constexpr int H = 128, Wd = 128;
constexpr int PLANE = H * Wd;          // 16384
constexpr int NBLOCKS = 32 * 64;       // 2048 planes
constexpr int WARPS = 8;
constexpr int RPW = H / WARPS;         // 16 rows per warp
constexpr int TBL = 9 * 25;            // 225 WL entries
}

struct RowS {
    float x[6];   // [0]=left edge, [1..4]=own 4 cols, [5]=right edge
    int   b[6];   // quantized bins for same
};

// Load row r (zeros if out of range) for this lane's 4-column strip,
// quantize, and fetch edge neighbors from adjacent lanes via shuffle.
__device__ __forceinline__ void load_row(const float* __restrict__ xp, int r,
                                         int lane, RowS& R) {
    float4 v = make_float4(0.f, 0.f, 0.f, 0.f);
    if ((unsigned)r < (unsigned)H)
        v = __ldg(reinterpret_cast<const float4*>(xp + r * Wd + lane * 4));
    R.x[1] = v.x; R.x[2] = v.y; R.x[3] = v.z; R.x[4] = v.w;
#pragma unroll
    for (int i = 1; i <= 4; ++i) {
        float t = fminf(R.x[i] * 5.0f, 4.0f);   // x>=0 here; floor==trunc
        R.b[i] = (int)t;
    }
    R.x[0] = __shfl_up_sync(0xffffffffu, v.w, 1);
    R.b[0] = __shfl_up_sync(0xffffffffu, R.b[4], 1);
    R.x[5] = __shfl_down_sync(0xffffffffu, v.x, 1);
    R.b[5] = __shfl_down_sync(0xffffffffu, R.b[1], 1);
    if (lane == 0)  { R.x[0] = 0.f; R.b[0] = 0; }
    if (lane == 31) { R.x[5] = 0.f; R.b[5] = 0; }
}

__global__ __launch_bounds__(256, 3)
void col_kernel(const float* __restrict__ x,
                const float* __restrict__ Wp,
                const float* __restrict__ Lp,
                float* __restrict__ out) {
    // Bank-replicated WL table: sWL[idx*32 + lane], idx = o*25 + bq*5 + bp.
    // Each lane only ever touches bank 'lane' -> conflict-free LDS.
    __shared__ float sWL[TBL * 32];

    for (int t = threadIdx.x; t < TBL * 32; t += 256) {
        int idx = t >> 5;
        int o = idx / 25;
        int i = idx - o * 25;
        sWL[t] = Wp[o] * Lp[i];
    }
    __syncthreads();

    const int plane = blockIdx.x;
    const float* xp = x + (size_t)plane * PLANE;
    float* op = out + (size_t)plane * PLANE;

    const int lane = threadIdx.x & 31;
    const int warp = threadIdx.x >> 5;
    const int r0 = warp * RPW;
    const char* laneBase = reinterpret_cast<const char*>(sWL) + lane * 4;

    RowS A, Bc, Cn;
    load_row(xp, r0 - 1, lane, A);
    load_row(xp, r0,     lane, Bc);

#pragma unroll 4
    for (int r = r0; r < r0 + RPW; ++r) {
        load_row(xp, r + 1, lane, Cn);

        float res[4];
#pragma unroll
        for (int i = 0; i < 4; ++i) {
            const int bp = Bc.b[i + 1];
            const char* pb = laneBase + bp * 128;  // + bp*32 floats
            float s = 0.f;
            // addr = laneBase + (o*25 + bq*5 + bp)*128 + lane*4
            //      = pb + bq*640 + o*3200 (o*3200 folds into LDS immediate)
#define COL_TERM(R, dh, dw)                                                     \
            s += *reinterpret_cast<const float*>(                               \
                     pb + (R).b[i + (dw)] * 640 + ((dh)*3 + (dw)) * 3200)       \
                 * (R).x[i + (dw)];
            COL_TERM(A,  0, 0) COL_TERM(A,  0, 1) COL_TERM(A,  0, 2)
            COL_TERM(Bc, 1, 0) COL_TERM(Bc, 1, 1) COL_TERM(Bc, 1, 2)
            COL_TERM(Cn, 2, 0) COL_TERM(Cn, 2, 1) COL_TERM(Cn, 2, 2)
#undef COL_TERM
            res[i] = s;
        }

        *reinterpret_cast<float4*>(op + r * Wd + lane * 4) =
            make_float4(res[0], res[1], res[2], res[3]);

        A = Bc;
        Bc = Cn;
    }
}

extern "C" void kernel_launch(void* const* d_in, const int* in_sizes, int n_in,
                              void* d_out, int out_size) {
    const float* x = nullptr;
    const float* W = nullptr;
    const float* L = nullptr;
    for (int i = 0; i < n_in; ++i) {
        if (in_sizes[i] == 9)       W = (const float*)d_in[i];
        else if (in_sizes[i] == 25) L = (const float*)d_in[i];
        else                        x = (const float*)d_in[i];
    }
    col_kernel<<<NBLOCKS, 256>>>(x, W, L, (float*)d_out);
}